// round 2
// baseline (speedup 1.0000x reference)
#include <cuda_runtime.h>
#include <cuda_bf16.h>

#define B_ 16
#define T_ 2048
#define L_ 128
#define H_ 512
#define M_IN 256
#define F_ 1024
#define LP 130                 // 128 ch + 1 const + 1 pad
#define C_CHUNK 16
#define Q_CHUNK 16
#define KTOT (C_CHUNK * LP)    // 2080
#define MZ (Q_CHUNK * B_)      // 256
#define NSPLIT 8
#define KPER 272               // 7*272=1904, last slice 176 (all mult of 16)

__device__ __align__(16) float g_U[KTOT * H_];
__device__ __align__(16) float g_P[4 * H_ * H_];    // A^2,A^4,A^8,A^16
__device__ __align__(16) float g_GT[H_ * H_];
__device__ __align__(16) float g_X[MZ * KTOT];
__device__ __align__(16) float g_Zp[NSPLIT * MZ * H_];
__device__ __align__(16) float g_Z[MZ * H_];
__device__ __align__(16) float g_S0[B_ * H_];
__device__ __align__(16) float g_S1[B_ * H_];

// U_0 = [We@Wb ; be@Wb ; 0]
__global__ void k_initW0(const float* __restrict__ We, const float* __restrict__ be,
                         const float* __restrict__ Wb) {
    int i = blockIdx.x * blockDim.x + threadIdx.x;
    if (i >= LP * H_) return;
    int l = i >> 9, h = i & 511;
    float acc = 0.f;
    if (l < 128) { for (int m = 0; m < M_IN; m++) acc += We[l * M_IN + m] * Wb[m * H_ + h]; }
    else if (l == 128) { for (int m = 0; m < M_IN; m++) acc += be[m] * Wb[m * H_ + h]; }
    g_U[i] = acc;
}

// C = A(MxK) @ B(Kx512), K-slice [z*kper, min(K,+kper)), slice z writes C+z*M*512
__global__ void k_sgemm(const float* __restrict__ A, const float* __restrict__ B,
                        float* __restrict__ C, int M, int K, int kper) {
    const int N = H_;
    int k0 = blockIdx.z * kper, k1 = k0 + kper; if (k1 > K) k1 = K;
    float* Cp = C + (size_t)blockIdx.z * M * N;
    __shared__ float As[64][17];
    __shared__ float Bs[16][64];
    int tx = threadIdx.x, ty = threadIdx.y, tid = ty * 16 + tx;
    int row0 = blockIdx.y * 64, col0 = blockIdx.x * 64;
    float acc[4][4] = {};
    int ar = tid >> 2, ak = (tid & 3) * 4;
    int brow = tid >> 4, bcol = (tid & 15) * 4;
    for (int kt = k0; kt < k1; kt += 16) {
        int r = row0 + ar;
        if (r < M) {
            const float* ap = A + (size_t)r * K + kt + ak;
            As[ar][ak] = ap[0]; As[ar][ak + 1] = ap[1]; As[ar][ak + 2] = ap[2]; As[ar][ak + 3] = ap[3];
        } else {
            As[ar][ak] = 0.f; As[ar][ak + 1] = 0.f; As[ar][ak + 2] = 0.f; As[ar][ak + 3] = 0.f;
        }
        *reinterpret_cast<float4*>(&Bs[brow][bcol]) =
            *reinterpret_cast<const float4*>(B + (size_t)(kt + brow) * N + col0 + bcol);
        __syncthreads();
        #pragma unroll
        for (int k = 0; k < 16; k++) {
            float a0 = As[ty * 4][k], a1 = As[ty * 4 + 1][k], a2 = As[ty * 4 + 2][k], a3 = As[ty * 4 + 3][k];
            float b0 = Bs[k][tx * 4], b1 = Bs[k][tx * 4 + 1], b2 = Bs[k][tx * 4 + 2], b3 = Bs[k][tx * 4 + 3];
            acc[0][0] += a0 * b0; acc[0][1] += a0 * b1; acc[0][2] += a0 * b2; acc[0][3] += a0 * b3;
            acc[1][0] += a1 * b0; acc[1][1] += a1 * b1; acc[1][2] += a1 * b2; acc[1][3] += a1 * b3;
            acc[2][0] += a2 * b0; acc[2][1] += a2 * b1; acc[2][2] += a2 * b2; acc[2][3] += a2 * b3;
            acc[3][0] += a3 * b0; acc[3][1] += a3 * b1; acc[3][2] += a3 * b2; acc[3][3] += a3 * b3;
        }
        __syncthreads();
    }
    #pragma unroll
    for (int i = 0; i < 4; i++) {
        int r = row0 + ty * 4 + i;
        if (r < M) {
            float* cp = Cp + (size_t)r * N + col0 + tx * 4;
            cp[0] = acc[i][0]; cp[1] = acc[i][1]; cp[2] = acc[i][2]; cp[3] = acc[i][3];
        }
    }
}

__global__ void k_transpose512(const float* __restrict__ in, float* __restrict__ out) {
    __shared__ float t[32][33];
    int bx = blockIdx.x * 32, by = blockIdx.y * 32;
    #pragma unroll
    for (int i = 0; i < 32; i += 8)
        t[threadIdx.y + i][threadIdx.x] = in[(size_t)(by + threadIdx.y + i) * H_ + bx + threadIdx.x];
    __syncthreads();
    #pragma unroll
    for (int i = 0; i < 32; i += 8)
        out[(size_t)(bx + threadIdx.y + i) * H_ + by + threadIdx.x] = t[threadIdx.x][threadIdx.y + i];
}

// X[m=q*16+b][kk=r*130+l] = x[b, 2047-(16q+r), l]; l=128 -> 1, l=129 -> 0
__global__ void k_gather(const float* __restrict__ x) {
    int i = blockIdx.x * blockDim.x + threadIdx.x;
    if (i >= MZ * KTOT) return;
    int m = i / KTOT, kk = i - m * KTOT;
    int r = kk / LP, l = kk - r * LP;
    int q = m >> 4, b = m & 15;
    float v;
    if (l < 128) v = x[((size_t)b * T_ + (T_ - 1) - (q * C_CHUNK + r)) * L_ + l];
    else v = (l == 128) ? 1.0f : 0.0f;
    g_X[i] = v;
}

__global__ void k_zreduce() {
    int i = blockIdx.x * blockDim.x + threadIdx.x;
    if (i >= MZ * H_) return;
    float a = 0.f;
    #pragma unroll
    for (int s = 0; s < NSPLIT; s++) a += g_Zp[s * (MZ * H_) + i];
    g_Z[i] = a;
}

__global__ void k_copy(const float* __restrict__ src, float* __restrict__ dst, int n) {
    int i = blockIdx.x * blockDim.x + threadIdx.x;
    if (i < n) dst[i] = src[i];
}

// S_out[b][h] = sum_k S_in[b][k]*G[k][h] + Zq[b][h], using GT[h][k]
__global__ void k_scan(const float* __restrict__ S_in, const float* __restrict__ Zq,
                       float* __restrict__ S_out) {
    __shared__ float Ssm[B_ * H_];
    int tid = threadIdx.x;
    for (int i = tid; i < B_ * H_; i += 256) Ssm[i] = S_in[i];
    __syncthreads();
    int w = tid >> 5, lane = tid & 31;
    int h = blockIdx.x * 8 + w;
    float acc[B_];
    #pragma unroll
    for (int b = 0; b < B_; b++) acc[b] = 0.f;
    const float* gt = g_GT + (size_t)h * H_;
    for (int k = lane; k < H_; k += 32) {
        float g = gt[k];
        #pragma unroll
        for (int b = 0; b < B_; b++) acc[b] += Ssm[b * H_ + k] * g;
    }
    #pragma unroll
    for (int b = 0; b < B_; b++) {
        float v = acc[b];
        #pragma unroll
        for (int o = 16; o; o >>= 1) v += __shfl_xor_sync(0xFFFFFFFFu, v, o);
        if (lane == 0) S_out[b * H_ + h] = v + Zq[b * H_ + h];
    }
}

__global__ void k_final(const float* __restrict__ S, const float* __restrict__ x,
                        const float* __restrict__ Wr, const float* __restrict__ br,
                        const float* __restrict__ lng, const float* __restrict__ lnb,
                        const float* __restrict__ W1, const float* __restrict__ b1,
                        const float* __restrict__ W2, const float* __restrict__ b2,
                        float* __restrict__ out) {
    int b = blockIdx.x, tid = threadIdx.x;
    __shared__ float xs[L_], z[H_], a[F_], r1[8], r2[8];
    __shared__ float mu_s, rs_s;
    if (tid < L_) xs[tid] = x[((size_t)b * T_ + (T_ - 1)) * L_ + tid];
    __syncthreads();
    for (int h = tid; h < H_; h += 256) {
        float acc = S[b * H_ + h] + br[h];
        for (int l = 0; l < L_; l++) acc += xs[l] * Wr[(size_t)l * H_ + h];
        z[h] = acc;
    }
    __syncthreads();
    float s1 = 0.f, s2 = 0.f;
    for (int h = tid; h < H_; h += 256) { float v = z[h]; s1 += v; s2 += v * v; }
    #pragma unroll
    for (int o = 16; o; o >>= 1) {
        s1 += __shfl_xor_sync(0xFFFFFFFFu, s1, o);
        s2 += __shfl_xor_sync(0xFFFFFFFFu, s2, o);
    }
    if ((tid & 31) == 0) { r1[tid >> 5] = s1; r2[tid >> 5] = s2; }
    __syncthreads();
    if (tid == 0) {
        float t1 = 0.f, t2 = 0.f;
        #pragma unroll
        for (int i = 0; i < 8; i++) { t1 += r1[i]; t2 += r2[i]; }
        float mu = t1 / (float)H_;
        mu_s = mu; rs_s = rsqrtf(t2 / (float)H_ - mu * mu + 1e-5f);
    }
    __syncthreads();
    for (int h = tid; h < H_; h += 256) z[h] = (z[h] - mu_s) * rs_s * lng[h] + lnb[h];
    __syncthreads();
    for (int f = tid; f < F_; f += 256) {
        float acc = b1[f];
        for (int h = 0; h < H_; h++) acc += z[h] * W1[(size_t)h * F_ + f];
        a[f] = fmaxf(acc, 0.f);
    }
    __syncthreads();
    for (int h2 = tid; h2 < H_; h2 += 256) {
        float acc = b2[h2];
        for (int f = 0; f < F_; f++) acc += a[f] * W2[(size_t)f * H_ + h2];
        out[b * H_ + h2] = acc;
    }
}

extern "C" void kernel_launch(void* const* d_in, const int* in_sizes, int n_in,
                              void* d_out, int out_size) {
    const float* x   = (const float*)d_in[0];
    const float* We  = (const float*)d_in[1];
    const float* be  = (const float*)d_in[2];
    const float* Wb  = (const float*)d_in[3];
    const float* A   = (const float*)d_in[4];
    const float* Wr  = (const float*)d_in[5];
    const float* br  = (const float*)d_in[6];
    const float* lng = (const float*)d_in[7];
    const float* lnb = (const float*)d_in[8];
    const float* W1  = (const float*)d_in[9];
    const float* b1  = (const float*)d_in[10];
    const float* W2  = (const float*)d_in[11];
    const float* b2  = (const float*)d_in[12];
    float* out = (float*)d_out;

    float *U, *P, *GT, *X, *Zp, *Z, *S0, *S1;
    cudaGetSymbolAddress((void**)&U,  g_U);
    cudaGetSymbolAddress((void**)&P,  g_P);
    cudaGetSymbolAddress((void**)&GT, g_GT);
    cudaGetSymbolAddress((void**)&X,  g_X);
    cudaGetSymbolAddress((void**)&Zp, g_Zp);
    cudaGetSymbolAddress((void**)&Z,  g_Z);
    cudaGetSymbolAddress((void**)&S0, g_S0);
    cudaGetSymbolAddress((void**)&S1, g_S1);
    float* P0 = P;                // A^2
    float* P1 = P + H_ * H_;      // A^4
    float* P2 = P + 2 * H_ * H_;  // A^8
    float* P3 = P + 3 * H_ * H_;  // A^16

    dim3 tb(16, 16);
    k_initW0<<<(LP * H_ + 255) / 256, 256>>>(We, be, Wb);
    k_gather<<<(MZ * KTOT + 255) / 256, 256>>>(x);

    // U doubling + power chain
    k_sgemm<<<dim3(8, 3, 1),  tb>>>(U, A,  U + 130 * H_, 130,  H_, H_);   // U1
    k_sgemm<<<dim3(8, 8, 1),  tb>>>(A, A,  P0, H_, H_, H_);               // A^2
    k_sgemm<<<dim3(8, 5, 1),  tb>>>(U, P0, U + 260 * H_, 260,  H_, H_);   // U2,3
    k_sgemm<<<dim3(8, 8, 1),  tb>>>(P0, P0, P1, H_, H_, H_);              // A^4
    k_sgemm<<<dim3(8, 9, 1),  tb>>>(U, P1, U + 520 * H_, 520,  H_, H_);   // U4..7
    k_sgemm<<<dim3(8, 8, 1),  tb>>>(P1, P1, P2, H_, H_, H_);              // A^8
    k_sgemm<<<dim3(8, 17, 1), tb>>>(U, P2, U + 1040 * H_, 1040, H_, H_);  // U8..15
    k_sgemm<<<dim3(8, 8, 1),  tb>>>(P2, P2, P3, H_, H_, H_);              // A^16
    k_transpose512<<<dim3(16, 16), dim3(32, 8)>>>(P3, GT);

    // Z = X @ U (split-K) then reduce
    k_sgemm<<<dim3(8, 4, NSPLIT), tb>>>(X, U, Zp, MZ, KTOT, KPER);
    k_zreduce<<<(MZ * H_ + 255) / 256, 256>>>();

    // Horner scan: S = Z_15; for q=14..0: S = S@G + Z_q
    k_copy<<<(B_ * H_ + 255) / 256, 256>>>(Z + 15 * B_ * H_, S0, B_ * H_);
    float* sin = S0; float* sout = S1;
    for (int q = 14; q >= 0; q--) {
        k_scan<<<H_ / 8, 256>>>(sin, Z + q * B_ * H_, sout);
        float* t = sin; sin = sout; sout = t;
    }
    // after 15 steps result is in `sin`
    k_final<<<B_, 256>>>(sin, x, Wr, br, lng, lnb, W1, b1, W2, b2, out);
}

// round 3
// speedup vs baseline: 1.4008x; 1.4008x over previous
#include <cuda_runtime.h>
#include <cuda_bf16.h>

#define B_ 16
#define T_ 2048
#define L_ 128
#define H_ 512
#define M_IN 256
#define F_ 1024
#define LP 130                 // 128 ch + 1 const + 1 pad
#define C_CHUNK 16
#define Q_CHUNK 16
#define KTOT (C_CHUNK * LP)    // 2080
#define MZ (Q_CHUNK * B_)      // 256
#define NSPLIT 8
#define KPER 272               // 7*272=1904, last slice 176 (mult of 16)
#define SCAN_BLOCKS 64

__device__ __align__(16) float g_U[KTOT * H_];
__device__ __align__(16) float g_P[4 * H_ * H_];    // A^2,A^4,A^8,A^16
__device__ __align__(16) float g_X[MZ * KTOT];
__device__ __align__(16) float g_Zp[NSPLIT * MZ * H_];
__device__ __align__(16) float g_S0[B_ * H_];
__device__ __align__(16) float g_S1[B_ * H_];
__device__ int g_cnt;
__device__ int g_gen;

// U_0 = [We@Wb ; be@Wb ; 0]
__global__ void k_initW0(const float* __restrict__ We, const float* __restrict__ be,
                         const float* __restrict__ Wb) {
    int i = blockIdx.x * blockDim.x + threadIdx.x;
    if (i >= LP * H_) return;
    int l = i >> 9, h = i & 511;
    float acc = 0.f;
    if (l < 128) { for (int m = 0; m < M_IN; m++) acc += We[l * M_IN + m] * Wb[m * H_ + h]; }
    else if (l == 128) { for (int m = 0; m < M_IN; m++) acc += be[m] * Wb[m * H_ + h]; }
    g_U[i] = acc;
}

// X[m=q*16+b][kk=r*130+l] = x[b, 2047-(16q+r), l]; l=128 -> 1, l=129 -> 0
__global__ void k_gather(const float* __restrict__ x) {
    int i = blockIdx.x * blockDim.x + threadIdx.x;
    if (i >= MZ * KTOT) return;
    int m = i / KTOT, kk = i - m * KTOT;
    int r = kk / LP, l = kk - r * LP;
    int q = m >> 4, b = m & 15;
    float v;
    if (l < 128) v = x[((size_t)b * T_ + (T_ - 1) - (q * C_CHUNK + r)) * L_ + l];
    else v = (l == 128) ? 1.0f : 0.0f;
    g_X[i] = v;
}

// Merged doubling stage: [Uout ; Pout] = [Urows(Mu) ; Prows(512)] @ B(512x512)
// Rows [0,Mu) read Urows / write Uout; rows [Mu, Mu+512) read Prows / write Pout.
__global__ void k_stage(const float* __restrict__ Urows, int Mu,
                        const float* __restrict__ Prows, const float* __restrict__ B,
                        float* __restrict__ Uout, float* __restrict__ Pout) {
    const int Mtot = Mu + H_;
    __shared__ float As[16][68];
    __shared__ float Bs[16][64];
    int tid = threadIdx.x;
    int tx = tid & 15, ty = tid >> 4;
    int row0 = blockIdx.y * 64, col0 = blockIdx.x * 64;
    float acc[4][4] = {};
    int ar = tid >> 2, ak = (tid & 3) << 2;
    int bcol = tx << 2;

    int r = row0 + ar;
    const float* arow = nullptr;
    if (r < Mtot) arow = (r < Mu) ? (Urows + (size_t)r * H_) : (Prows + (size_t)(r - Mu) * H_);
    const float* brow = B + (size_t)ty * H_ + col0 + bcol;

    for (int kt = 0; kt < H_; kt += 16) {
        float4 av = arow ? *(const float4*)(arow + kt + ak) : make_float4(0.f, 0.f, 0.f, 0.f);
        As[ak + 0][ar] = av.x; As[ak + 1][ar] = av.y;
        As[ak + 2][ar] = av.z; As[ak + 3][ar] = av.w;
        *(float4*)&Bs[ty][bcol] = *(const float4*)(brow + (size_t)kt * H_);
        __syncthreads();
        #pragma unroll
        for (int k = 0; k < 16; k++) {
            float4 a = *(const float4*)&As[k][ty << 2];
            float4 b = *(const float4*)&Bs[k][bcol];
            acc[0][0] += a.x * b.x; acc[0][1] += a.x * b.y; acc[0][2] += a.x * b.z; acc[0][3] += a.x * b.w;
            acc[1][0] += a.y * b.x; acc[1][1] += a.y * b.y; acc[1][2] += a.y * b.z; acc[1][3] += a.y * b.w;
            acc[2][0] += a.z * b.x; acc[2][1] += a.z * b.y; acc[2][2] += a.z * b.z; acc[2][3] += a.z * b.w;
            acc[3][0] += a.w * b.x; acc[3][1] += a.w * b.y; acc[3][2] += a.w * b.z; acc[3][3] += a.w * b.w;
        }
        __syncthreads();
    }
    #pragma unroll
    for (int i = 0; i < 4; i++) {
        int rr = row0 + (ty << 2) + i;
        if (rr < Mtot) {
            float* orow = (rr < Mu) ? (Uout + (size_t)rr * H_) : (Pout + (size_t)(rr - Mu) * H_);
            *(float4*)(orow + col0 + bcol) = make_float4(acc[i][0], acc[i][1], acc[i][2], acc[i][3]);
        }
    }
}

// Zp[z] = X(256 x KTOT) @ U, K-slice [z*KPER, min(KTOT, +KPER))
__global__ void k_zgemm() {
    int k0 = blockIdx.z * KPER, k1 = k0 + KPER; if (k1 > KTOT) k1 = KTOT;
    float* Cp = g_Zp + (size_t)blockIdx.z * MZ * H_;
    __shared__ float As[16][68];
    __shared__ float Bs[16][64];
    int tid = threadIdx.x;
    int tx = tid & 15, ty = tid >> 4;
    int row0 = blockIdx.y * 64, col0 = blockIdx.x * 64;
    float acc[4][4] = {};
    int ar = tid >> 2, ak = (tid & 3) << 2;
    int bcol = tx << 2;
    const float* arow = g_X + (size_t)(row0 + ar) * KTOT;
    for (int kt = k0; kt < k1; kt += 16) {
        float4 av = *(const float4*)(arow + kt + ak);
        As[ak + 0][ar] = av.x; As[ak + 1][ar] = av.y;
        As[ak + 2][ar] = av.z; As[ak + 3][ar] = av.w;
        *(float4*)&Bs[ty][bcol] = *(const float4*)(g_U + (size_t)(kt + ty) * H_ + col0 + bcol);
        __syncthreads();
        #pragma unroll
        for (int k = 0; k < 16; k++) {
            float4 a = *(const float4*)&As[k][ty << 2];
            float4 b = *(const float4*)&Bs[k][bcol];
            acc[0][0] += a.x * b.x; acc[0][1] += a.x * b.y; acc[0][2] += a.x * b.z; acc[0][3] += a.x * b.w;
            acc[1][0] += a.y * b.x; acc[1][1] += a.y * b.y; acc[1][2] += a.y * b.z; acc[1][3] += a.y * b.w;
            acc[2][0] += a.z * b.x; acc[2][1] += a.z * b.y; acc[2][2] += a.z * b.z; acc[2][3] += a.z * b.w;
            acc[3][0] += a.w * b.x; acc[3][1] += a.w * b.y; acc[3][2] += a.w * b.z; acc[3][3] += a.w * b.w;
        }
        __syncthreads();
    }
    #pragma unroll
    for (int i = 0; i < 4; i++) {
        float* cp = Cp + (size_t)(row0 + (ty << 2) + i) * H_ + col0 + bcol;
        *(float4*)cp = make_float4(acc[i][0], acc[i][1], acc[i][2], acc[i][3]);
    }
}

__global__ void k_barinit() { if (threadIdx.x == 0) { g_cnt = 0; g_gen = 0; } }

__device__ __forceinline__ void gridbar(int it) {
    __syncthreads();
    __threadfence();
    if (threadIdx.x == 0) {
        int t = atomicAdd(&g_cnt, 1);
        if (t == SCAN_BLOCKS - 1) {
            atomicExch(&g_cnt, 0);
            __threadfence();
            atomicAdd(&g_gen, 1);
        }
        while (*(volatile int*)&g_gen < it + 1) {}
    }
    __syncthreads();
}

// Single-launch Horner scan: S = Z_15; for q=14..0: S = S@G + Z_q (G = A^16).
// 64 all-resident blocks, software grid barrier. Z split-K reduce fused in.
__global__ void k_scanall() {
    __shared__ float Ssm[4][H_];
    __shared__ float red[8][128];
    const float* Gm = g_P + 3 * H_ * H_;
    int tid = threadIdx.x;
    int bg = blockIdx.x >> 4;          // 4 batch rows per block
    int hg = blockIdx.x & 15;          // 32 h-cols per block
    int hslot = tid & 7;               // 4 h each
    int bsl = (tid >> 3) & 3;
    int krep = tid >> 5;               // k range [krep*64, +64)
    int h = hg * 32 + hslot * 4;

    for (int i = 0; i < 16; i++) {
        int q = 15 - i;
        if (i > 0) {
            const float* Sin = ((i - 1) & 1) ? g_S1 : g_S0;
            for (int t = tid; t < 4 * H_; t += 256)
                Ssm[t >> 9][t & 511] = Sin[(bg * 4 + (t >> 9)) * H_ + (t & 511)];
            __syncthreads();
        }
        float a0 = 0.f, a1 = 0.f, a2 = 0.f, a3 = 0.f;
        if (i > 0) {
            const float* gp = Gm + (size_t)(krep * 64) * H_ + h;
            const float* srow = &Ssm[bsl][krep * 64];
            #pragma unroll 8
            for (int k = 0; k < 64; k++) {
                float4 g = *(const float4*)(gp + (size_t)k * H_);
                float s = srow[k];
                a0 += s * g.x; a1 += s * g.y; a2 += s * g.z; a3 += s * g.w;
            }
        }
        int oi = bsl * 32 + hslot * 4;
        red[krep][oi + 0] = a0; red[krep][oi + 1] = a1;
        red[krep][oi + 2] = a2; red[krep][oi + 3] = a3;
        __syncthreads();
        if (tid < 128) {
            int ob = tid >> 5, oh = tid & 31;
            float v = 0.f;
            #pragma unroll
            for (int s = 0; s < 8; s++) v += red[s][tid];
            int m = q * 16 + bg * 4 + ob;
            int hc = hg * 32 + oh;
            float z = 0.f;
            #pragma unroll
            for (int s = 0; s < NSPLIT; s++) z += g_Zp[(size_t)s * (MZ * H_) + (size_t)m * H_ + hc];
            float* Sout = (i & 1) ? g_S1 : g_S0;
            Sout[(bg * 4 + ob) * H_ + hc] = v + z;
        }
        if (i < 15) gridbar(i);
    }
}

__global__ void k_final(const float* __restrict__ S, const float* __restrict__ x,
                        const float* __restrict__ Wr, const float* __restrict__ br,
                        const float* __restrict__ lng, const float* __restrict__ lnb,
                        const float* __restrict__ W1, const float* __restrict__ b1,
                        const float* __restrict__ W2, const float* __restrict__ b2,
                        float* __restrict__ out) {
    int b = blockIdx.x, tid = threadIdx.x;
    __shared__ float xs[L_], z[H_], a[F_], r1[8], r2[8];
    __shared__ float mu_s, rs_s;
    if (tid < L_) xs[tid] = x[((size_t)b * T_ + (T_ - 1)) * L_ + tid];
    __syncthreads();
    for (int h = tid; h < H_; h += 256) {
        float acc = S[b * H_ + h] + br[h];
        for (int l = 0; l < L_; l++) acc += xs[l] * Wr[(size_t)l * H_ + h];
        z[h] = acc;
    }
    __syncthreads();
    float s1 = 0.f, s2 = 0.f;
    for (int h = tid; h < H_; h += 256) { float v = z[h]; s1 += v; s2 += v * v; }
    #pragma unroll
    for (int o = 16; o; o >>= 1) {
        s1 += __shfl_xor_sync(0xFFFFFFFFu, s1, o);
        s2 += __shfl_xor_sync(0xFFFFFFFFu, s2, o);
    }
    if ((tid & 31) == 0) { r1[tid >> 5] = s1; r2[tid >> 5] = s2; }
    __syncthreads();
    if (tid == 0) {
        float t1 = 0.f, t2 = 0.f;
        #pragma unroll
        for (int i = 0; i < 8; i++) { t1 += r1[i]; t2 += r2[i]; }
        float mu = t1 / (float)H_;
        mu_s = mu; rs_s = rsqrtf(t2 / (float)H_ - mu * mu + 1e-5f);
    }
    __syncthreads();
    for (int h = tid; h < H_; h += 256) z[h] = (z[h] - mu_s) * rs_s * lng[h] + lnb[h];
    __syncthreads();
    for (int f = tid; f < F_; f += 256) {
        float acc = b1[f];
        for (int h = 0; h < H_; h++) acc += z[h] * W1[(size_t)h * F_ + f];
        a[f] = fmaxf(acc, 0.f);
    }
    __syncthreads();
    for (int h2 = tid; h2 < H_; h2 += 256) {
        float acc = b2[h2];
        for (int f = 0; f < F_; f++) acc += a[f] * W2[(size_t)f * H_ + h2];
        out[b * H_ + h2] = acc;
    }
}

extern "C" void kernel_launch(void* const* d_in, const int* in_sizes, int n_in,
                              void* d_out, int out_size) {
    const float* x   = (const float*)d_in[0];
    const float* We  = (const float*)d_in[1];
    const float* be  = (const float*)d_in[2];
    const float* Wb  = (const float*)d_in[3];
    const float* A   = (const float*)d_in[4];
    const float* Wr  = (const float*)d_in[5];
    const float* br  = (const float*)d_in[6];
    const float* lng = (const float*)d_in[7];
    const float* lnb = (const float*)d_in[8];
    const float* W1  = (const float*)d_in[9];
    const float* b1  = (const float*)d_in[10];
    const float* W2  = (const float*)d_in[11];
    const float* b2  = (const float*)d_in[12];
    float* out = (float*)d_out;

    float *U, *P, *S1;
    cudaGetSymbolAddress((void**)&U,  g_U);
    cudaGetSymbolAddress((void**)&P,  g_P);
    cudaGetSymbolAddress((void**)&S1, g_S1);
    float* P0 = P;                // A^2
    float* P1 = P + H_ * H_;      // A^4
    float* P2 = P + 2 * H_ * H_;  // A^8
    float* P3 = P + 3 * H_ * H_;  // A^16

    k_initW0<<<(LP * H_ + 255) / 256, 256>>>(We, be, Wb);
    k_gather<<<(MZ * KTOT + 255) / 256, 256>>>(x);

    // merged doubling + power chain: [U_new ; A^(2s)] = [U_prev ; A^s] @ A^s
    k_stage<<<dim3(8, 11), 256>>>(U, 130,  A,  A,  U + 130 * H_,  P0);  // M=642
    k_stage<<<dim3(8, 13), 256>>>(U, 260,  P0, P0, U + 260 * H_,  P1);  // M=772
    k_stage<<<dim3(8, 17), 256>>>(U, 520,  P1, P1, U + 520 * H_,  P2);  // M=1032
    k_stage<<<dim3(8, 25), 256>>>(U, 1040, P2, P2, U + 1040 * H_, P3);  // M=1552

    // Z = X @ U, split-K (partials consumed directly by the scan)
    k_zgemm<<<dim3(8, 4, NSPLIT), 256>>>();

    // single-launch Horner scan over q=15..0
    k_barinit<<<1, 32>>>();
    k_scanall<<<SCAN_BLOCKS, 256>>>();

    // after 16 iters (last i=15, odd) the state is in g_S1
    k_final<<<B_, 256>>>(S1, x, Wr, br, lng, lnb, W1, b1, W2, b2, out);
}

// round 5
// speedup vs baseline: 1.6494x; 1.1775x over previous
#include <cuda_runtime.h>
#include <cuda_bf16.h>
#include <cstdint>

#define B_ 16
#define T_ 2048
#define L_ 128
#define H_ 512
#define M_IN 256
#define F_ 1024
#define LP 130                 // 128 ch + 1 const + 1 pad
#define C_CHUNK 16
#define Q_CHUNK 16
#define KTOT (C_CHUNK * LP)    // 2080
#define MZ (Q_CHUNK * B_)      // 256
#define NSPLIT 8
#define KPER 288               // 7*288=2016, last slice 64 (mult of 32)
#define SCAN_BLOCKS 64

typedef __nv_bfloat16 bf16;

__device__ __align__(16) bf16 g_A0h[H_ * H_], g_A0l[H_ * H_];
__device__ __align__(16) bf16 g_Uh[KTOT * H_], g_Ul[KTOT * H_];
__device__ __align__(16) bf16 g_Ph[4 * H_ * H_], g_Pl[4 * H_ * H_];
__device__ __align__(16) bf16 g_Xh[MZ * KTOT], g_Xl[MZ * KTOT];
__device__ __align__(16) float g_Gf[H_ * H_];
__device__ __align__(16) float g_Zp[NSPLIT * MZ * H_];
__device__ __align__(16) float g_S0[B_ * H_], g_S1[B_ * H_];
__device__ int g_cnt;
__device__ int g_gen;

__device__ __forceinline__ void splitw(float v, bf16* ph, bf16* pl) {
    bf16 h = __float2bfloat16(v);
    *ph = h;
    *pl = __float2bfloat16(v - __bfloat162float(h));
}

// ---------------------------------------------------------------------------
__global__ void k_splitA(const float* __restrict__ A) {
    int i = blockIdx.x * blockDim.x + threadIdx.x;
    if (i >= H_ * H_) return;
    splitw(A[i], &g_A0h[i], &g_A0l[i]);
}

// U_0 = [We@Wb ; be@Wb ; 0] -> bf16 hi/lo
__global__ void k_initW0(const float* __restrict__ We, const float* __restrict__ be,
                         const float* __restrict__ Wb) {
    int i = blockIdx.x * blockDim.x + threadIdx.x;
    if (i >= LP * H_) return;
    int l = i >> 9, h = i & 511;
    float acc = 0.f;
    if (l < 128) { for (int m = 0; m < M_IN; m++) acc += We[l * M_IN + m] * Wb[m * H_ + h]; }
    else if (l == 128) { for (int m = 0; m < M_IN; m++) acc += be[m] * Wb[m * H_ + h]; }
    splitw(acc, &g_Uh[i], &g_Ul[i]);
}

// X[m=q*16+b][kk=r*130+l] = x[b, 2047-(16q+r), l]; l=128 -> 1, l=129 -> 0
__global__ void k_gather(const float* __restrict__ x) {
    int i = blockIdx.x * blockDim.x + threadIdx.x;
    if (i >= MZ * KTOT) return;
    int m = i / KTOT, kk = i - m * KTOT;
    int r = kk / LP, l = kk - r * LP;
    int q = m >> 4, b = m & 15;
    float v;
    if (l < 128) v = x[((size_t)b * T_ + (T_ - 1) - (q * C_CHUNK + r)) * L_ + l];
    else v = (l == 128) ? 1.0f : 0.0f;
    splitw(v, &g_Xh[i], &g_Xl[i]);
}

// ---------------------------------------------------------------------------
__device__ __forceinline__ void ldsm4(uint32_t* r, const void* p) {
    uint32_t addr = (uint32_t)__cvta_generic_to_shared(p);
    asm volatile("ldmatrix.sync.aligned.m8n8.x4.shared.b16 {%0,%1,%2,%3}, [%4];"
                 : "=r"(r[0]), "=r"(r[1]), "=r"(r[2]), "=r"(r[3]) : "r"(addr));
}
__device__ __forceinline__ void ldsm4t(uint32_t* r, const void* p) {
    uint32_t addr = (uint32_t)__cvta_generic_to_shared(p);
    asm volatile("ldmatrix.sync.aligned.m8n8.x4.trans.shared.b16 {%0,%1,%2,%3}, [%4];"
                 : "=r"(r[0]), "=r"(r[1]), "=r"(r[2]), "=r"(r[3]) : "r"(addr));
}
__device__ __forceinline__ void mma16816(float* d, const uint32_t* a, const uint32_t* b) {
    asm volatile("mma.sync.aligned.m16n8k16.row.col.f32.bf16.bf16.f32 "
                 "{%0,%1,%2,%3}, {%4,%5,%6,%7}, {%8,%9}, {%0,%1,%2,%3};"
                 : "+f"(d[0]), "+f"(d[1]), "+f"(d[2]), "+f"(d[3])
                 : "r"(a[0]), "r"(a[1]), "r"(a[2]), "r"(a[3]), "r"(b[0]), "r"(b[1]));
}

// C[M x 512] = A[M x K] @ B[K x 512], all operands bf16 hi/lo pairs.
// A rows r < Mu come from A1*, else A2* (row r-Mu). Outputs: bf16 hi/lo to
// C1*/C2* (nullable) and fp32 to C1f/C2f (nullable). grid.z = split-K slice.
__global__ __launch_bounds__(256) void k_tgemm(
    const bf16* __restrict__ A1h, const bf16* __restrict__ A1l,
    const bf16* __restrict__ A2h, const bf16* __restrict__ A2l,
    int Mu, int Mtot, int lda,
    const bf16* __restrict__ Bhg, const bf16* __restrict__ Blg,
    bf16* C1h, bf16* C1l, bf16* C2h, bf16* C2l,
    float* C1f, float* C2f,
    int kper, int K)
{
    __shared__ __align__(16) bf16 Ash[128][40];
    __shared__ __align__(16) bf16 Asl[128][40];
    __shared__ __align__(16) bf16 Bsh[32][72];
    __shared__ __align__(16) bf16 Bsl[32][72];

    int tid = threadIdx.x;
    int lane = tid & 31, wid = tid >> 5;
    int wm = wid & 3, wn = wid >> 2;
    int row0 = blockIdx.y * 128, col0 = blockIdx.x * 64;
    int k0 = blockIdx.z * kper, k1 = k0 + kper; if (k1 > K) k1 = K;
    size_t coff = (size_t)blockIdx.z * Mtot * H_;

    float acc[2][4][4];
    #pragma unroll
    for (int a = 0; a < 2; a++)
        #pragma unroll
        for (int b = 0; b < 4; b++)
            #pragma unroll
            for (int c = 0; c < 4; c++) acc[a][b][c] = 0.f;

    // fragment lane addressing
    int a_r = (lane & 7) + (lane & 8);
    int a_c = (lane & 16) ? 8 : 0;
    // B (trans): lanes 0-7 -> (k0..7, n+0), 8-15 -> (k8..15, n+0),
    //            16-23 -> (k0..7, n+8), 24-31 -> (k8..15, n+8)
    // so regs come out {k0n0, k8n0, k0n8, k8n8}: contiguous pairs are the
    // correct mma B fragments for n-blocks 0 and 8.
    int b_r = (lane & 7) + (lane & 8);
    int b_c = (lane & 16) ? 8 : 0;

    // staging indices: A tile 128x32 bf16 = 512 uint4 -> 2/thread per buffer
    // B tile 32x64 = 256 uint4 -> 1/thread per buffer
    int sb_k = tid >> 3, sb_n = (tid & 7) * 8;

    for (int kt = k0; kt < k1; kt += 32) {
        #pragma unroll
        for (int p = 0; p < 2; p++) {
            int idx = p * 256 + tid;
            int m = idx >> 2, c8 = (idx & 3) * 8;
            int r = row0 + m;
            uint4 vh = make_uint4(0, 0, 0, 0), vl = make_uint4(0, 0, 0, 0);
            if (r < Mtot) {
                size_t off = (r < Mu) ? ((size_t)r * lda + kt + c8)
                                      : ((size_t)(r - Mu) * lda + kt + c8);
                const bf16* sh = (r < Mu) ? A1h : A2h;
                const bf16* sl = (r < Mu) ? A1l : A2l;
                vh = *(const uint4*)(sh + off);
                vl = *(const uint4*)(sl + off);
            }
            *(uint4*)&Ash[m][c8] = vh;
            *(uint4*)&Asl[m][c8] = vl;
        }
        {
            size_t off = (size_t)(kt + sb_k) * H_ + col0 + sb_n;
            *(uint4*)&Bsh[sb_k][sb_n] = *(const uint4*)(Bhg + off);
            *(uint4*)&Bsl[sb_k][sb_n] = *(const uint4*)(Blg + off);
        }
        __syncthreads();

        #pragma unroll
        for (int ks = 0; ks < 2; ks++) {
            int kc = ks * 16;
            uint32_t ah[2][4], al[2][4], bh[2][4], bl[2][4];
            #pragma unroll
            for (int mt = 0; mt < 2; mt++) {
                int mr = wm * 32 + mt * 16 + a_r;
                ldsm4(ah[mt], &Ash[mr][kc + a_c]);
                ldsm4(al[mt], &Asl[mr][kc + a_c]);
            }
            #pragma unroll
            for (int pr = 0; pr < 2; pr++) {
                int nb = wn * 32 + pr * 16 + b_c;
                ldsm4t(bh[pr], &Bsh[kc + b_r][nb]);
                ldsm4t(bl[pr], &Bsl[kc + b_r][nb]);
            }
            #pragma unroll
            for (int mt = 0; mt < 2; mt++)
                #pragma unroll
                for (int nt = 0; nt < 4; nt++) {
                    const uint32_t* bhf = &bh[nt >> 1][(nt & 1) * 2];
                    const uint32_t* blf = &bl[nt >> 1][(nt & 1) * 2];
                    mma16816(acc[mt][nt], ah[mt], bhf);
                    mma16816(acc[mt][nt], ah[mt], blf);
                    mma16816(acc[mt][nt], al[mt], bhf);
                }
        }
        __syncthreads();
    }

    #pragma unroll
    for (int mt = 0; mt < 2; mt++)
        #pragma unroll
        for (int nt = 0; nt < 4; nt++) {
            int c = col0 + wn * 32 + nt * 8 + (lane & 3) * 2;
            #pragma unroll
            for (int half = 0; half < 2; half++) {
                int r = row0 + wm * 32 + mt * 16 + (lane >> 2) + half * 8;
                if (r >= Mtot) continue;
                float v0 = acc[mt][nt][half * 2], v1 = acc[mt][nt][half * 2 + 1];
                bool lo = (r < Mu);
                size_t ro = lo ? (size_t)r * H_ : (size_t)(r - Mu) * H_;
                bf16* ch = lo ? C1h : C2h;
                bf16* cl = lo ? C1l : C2l;
                float* cf = lo ? C1f : C2f;
                if (ch) {
                    splitw(v0, &ch[coff + ro + c], &cl[coff + ro + c]);
                    splitw(v1, &ch[coff + ro + c + 1], &cl[coff + ro + c + 1]);
                }
                if (cf) { cf[coff + ro + c] = v0; cf[coff + ro + c + 1] = v1; }
            }
        }
}

// ---------------------------------------------------------------------------
__global__ void k_barinit() { if (threadIdx.x == 0) { g_cnt = 0; g_gen = 0; } }

__device__ __forceinline__ void gridbar(int it) {
    __syncthreads();
    __threadfence();
    if (threadIdx.x == 0) {
        int t = atomicAdd(&g_cnt, 1);
        if (t == SCAN_BLOCKS - 1) {
            atomicExch(&g_cnt, 0);
            __threadfence();
            atomicAdd(&g_gen, 1);
        }
        while (*(volatile int*)&g_gen < it + 1) {}
    }
    __syncthreads();
}

// Horner scan: S = Z_15; for q=14..0: S = S@G + Z_q, G = A^16 (fp32).
// 64 resident blocks; block = (bg: 4 batches) x (hg: 32 h cols).
// thread = (krep 0..31: 16 k) x (hslot 0..7: 4 h); batch looped in registers.
__global__ __launch_bounds__(256) void k_scanall() {
    __shared__ float Ssm[4][H_];
    __shared__ float red[32][128];
    int tid = threadIdx.x;
    int bg = blockIdx.x >> 4;
    int hg = blockIdx.x & 15;
    int krep = tid >> 3;
    int hslot = tid & 7;
    int h = hg * 32 + hslot * 4;
    const float* gp = g_Gf + (size_t)(krep * 16) * H_ + h;

    for (int i = 0; i < 16; i++) {
        int q = 15 - i;
        float a0[4] = {}, a1[4] = {}, a2[4] = {}, a3[4] = {};
        if (i > 0) {
            const float* Sin = ((i - 1) & 1) ? g_S1 : g_S0;
            for (int t = tid; t < 4 * H_; t += 256)
                Ssm[t >> 9][t & 511] = Sin[(bg * 4 + (t >> 9)) * H_ + (t & 511)];
            __syncthreads();
            #pragma unroll 4
            for (int kk = 0; kk < 16; kk++) {
                int k = (kk + krep) & 15;   // stagger: kill Ssm bank conflicts
                float4 g = *(const float4*)(gp + (size_t)k * H_);
                float s0 = Ssm[0][krep * 16 + k];
                float s1 = Ssm[1][krep * 16 + k];
                float s2 = Ssm[2][krep * 16 + k];
                float s3 = Ssm[3][krep * 16 + k];
                a0[0] += s0 * g.x; a0[1] += s0 * g.y; a0[2] += s0 * g.z; a0[3] += s0 * g.w;
                a1[0] += s1 * g.x; a1[1] += s1 * g.y; a1[2] += s1 * g.z; a1[3] += s1 * g.w;
                a2[0] += s2 * g.x; a2[1] += s2 * g.y; a2[2] += s2 * g.z; a2[3] += s2 * g.w;
                a3[0] += s3 * g.x; a3[1] += s3 * g.y; a3[2] += s3 * g.z; a3[3] += s3 * g.w;
            }
        }
        *(float4*)&red[krep][0 * 32 + hslot * 4] = *(float4*)a0;
        *(float4*)&red[krep][1 * 32 + hslot * 4] = *(float4*)a1;
        *(float4*)&red[krep][2 * 32 + hslot * 4] = *(float4*)a2;
        *(float4*)&red[krep][3 * 32 + hslot * 4] = *(float4*)a3;
        __syncthreads();
        if (tid < 128) {
            float v = 0.f;
            #pragma unroll
            for (int s = 0; s < 32; s++) v += red[s][tid];
            int b = tid >> 5, hcl = tid & 31;
            int m = q * 16 + bg * 4 + b;
            int hc = hg * 32 + hcl;
            float z = 0.f;
            #pragma unroll
            for (int s2 = 0; s2 < NSPLIT; s2++)
                z += g_Zp[(size_t)s2 * (MZ * H_) + (size_t)m * H_ + hc];
            float* Sout = (i & 1) ? g_S1 : g_S0;
            Sout[(bg * 4 + b) * H_ + hc] = v + z;
        }
        if (i < 15) gridbar(i);
    }
}

// ---------------------------------------------------------------------------
__global__ void k_final(const float* __restrict__ S, const float* __restrict__ x,
                        const float* __restrict__ Wr, const float* __restrict__ br,
                        const float* __restrict__ lng, const float* __restrict__ lnb,
                        const float* __restrict__ W1, const float* __restrict__ b1,
                        const float* __restrict__ W2, const float* __restrict__ b2,
                        float* __restrict__ out) {
    int b = blockIdx.x, tid = threadIdx.x;
    __shared__ float xs[L_], z[H_], a[F_], r1[8], r2[8];
    __shared__ float mu_s, rs_s;
    if (tid < L_) xs[tid] = x[((size_t)b * T_ + (T_ - 1)) * L_ + tid];
    __syncthreads();
    for (int h = tid; h < H_; h += 256) {
        float acc = S[b * H_ + h] + br[h];
        for (int l = 0; l < L_; l++) acc += xs[l] * Wr[(size_t)l * H_ + h];
        z[h] = acc;
    }
    __syncthreads();
    float s1 = 0.f, s2 = 0.f;
    for (int h = tid; h < H_; h += 256) { float v = z[h]; s1 += v; s2 += v * v; }
    #pragma unroll
    for (int o = 16; o; o >>= 1) {
        s1 += __shfl_xor_sync(0xFFFFFFFFu, s1, o);
        s2 += __shfl_xor_sync(0xFFFFFFFFu, s2, o);
    }
    if ((tid & 31) == 0) { r1[tid >> 5] = s1; r2[tid >> 5] = s2; }
    __syncthreads();
    if (tid == 0) {
        float t1 = 0.f, t2 = 0.f;
        #pragma unroll
        for (int i = 0; i < 8; i++) { t1 += r1[i]; t2 += r2[i]; }
        float mu = t1 / (float)H_;
        mu_s = mu; rs_s = rsqrtf(t2 / (float)H_ - mu * mu + 1e-5f);
    }
    __syncthreads();
    for (int h = tid; h < H_; h += 256) z[h] = (z[h] - mu_s) * rs_s * lng[h] + lnb[h];
    __syncthreads();
    for (int f = tid; f < F_; f += 256) {
        float acc = b1[f];
        for (int h = 0; h < H_; h++) acc += z[h] * W1[(size_t)h * F_ + f];
        a[f] = fmaxf(acc, 0.f);
    }
    __syncthreads();
    for (int h2 = tid; h2 < H_; h2 += 256) {
        float acc = b2[h2];
        for (int f = 0; f < F_; f++) acc += a[f] * W2[(size_t)f * H_ + h2];
        out[b * H_ + h2] = acc;
    }
}

// ---------------------------------------------------------------------------
extern "C" void kernel_launch(void* const* d_in, const int* in_sizes, int n_in,
                              void* d_out, int out_size) {
    const float* x   = (const float*)d_in[0];
    const float* We  = (const float*)d_in[1];
    const float* be  = (const float*)d_in[2];
    const float* Wb  = (const float*)d_in[3];
    const float* A   = (const float*)d_in[4];
    const float* Wr  = (const float*)d_in[5];
    const float* br  = (const float*)d_in[6];
    const float* lng = (const float*)d_in[7];
    const float* lnb = (const float*)d_in[8];
    const float* W1  = (const float*)d_in[9];
    const float* b1  = (const float*)d_in[10];
    const float* W2  = (const float*)d_in[11];
    const float* b2  = (const float*)d_in[12];
    float* out = (float*)d_out;

    bf16 *A0h, *A0l, *Uh, *Ul, *Ph, *Pl, *Xh, *Xl;
    float *Gf, *Zp, *S1;
    cudaGetSymbolAddress((void**)&A0h, g_A0h);
    cudaGetSymbolAddress((void**)&A0l, g_A0l);
    cudaGetSymbolAddress((void**)&Uh,  g_Uh);
    cudaGetSymbolAddress((void**)&Ul,  g_Ul);
    cudaGetSymbolAddress((void**)&Ph,  g_Ph);
    cudaGetSymbolAddress((void**)&Pl,  g_Pl);
    cudaGetSymbolAddress((void**)&Xh,  g_Xh);
    cudaGetSymbolAddress((void**)&Xl,  g_Xl);
    cudaGetSymbolAddress((void**)&Gf,  g_Gf);
    cudaGetSymbolAddress((void**)&Zp,  g_Zp);
    cudaGetSymbolAddress((void**)&S1,  g_S1);

    bf16* P0h = Ph;               bf16* P0l = Pl;                // A^2
    bf16* P1h = Ph + H_ * H_;     bf16* P1l = Pl + H_ * H_;      // A^4
    bf16* P2h = Ph + 2 * H_ * H_; bf16* P2l = Pl + 2 * H_ * H_;  // A^8
    bf16* P3h = Ph + 3 * H_ * H_; bf16* P3l = Pl + 3 * H_ * H_;  // A^16

    k_splitA<<<(H_ * H_ + 255) / 256, 256>>>(A);
    k_initW0<<<(LP * H_ + 255) / 256, 256>>>(We, be, Wb);
    k_gather<<<(MZ * KTOT + 255) / 256, 256>>>(x);

    // merged doubling + power chain: [U_new ; A^(2s)] = [U_prev ; A^s] @ A^s
    k_tgemm<<<dim3(8, 6), 256>>>(Uh, Ul, A0h, A0l, 130, 642, H_, A0h, A0l,
        Uh + 130 * H_, Ul + 130 * H_, P0h, P0l, nullptr, nullptr, 512, 512);
    k_tgemm<<<dim3(8, 7), 256>>>(Uh, Ul, P0h, P0l, 260, 772, H_, P0h, P0l,
        Uh + 260 * H_, Ul + 260 * H_, P1h, P1l, nullptr, nullptr, 512, 512);
    k_tgemm<<<dim3(8, 9), 256>>>(Uh, Ul, P1h, P1l, 520, 1032, H_, P1h, P1l,
        Uh + 520 * H_, Ul + 520 * H_, P2h, P2l, nullptr, nullptr, 512, 512);
    k_tgemm<<<dim3(8, 13), 256>>>(Uh, Ul, P2h, P2l, 1040, 1552, H_, P2h, P2l,
        Uh + 1040 * H_, Ul + 1040 * H_, P3h, P3l, nullptr, Gf, 512, 512);

    // Z = X @ U, split-K -> fp32 partials (consumed by the scan)
    k_tgemm<<<dim3(8, 2, NSPLIT), 256>>>(Xh, Xl, Xh, Xl, MZ, MZ, KTOT, Uh, Ul,
        nullptr, nullptr, nullptr, nullptr, Zp, nullptr, KPER, KTOT);

    // single-launch Horner scan over q=15..0
    k_barinit<<<1, 32>>>();
    k_scanall<<<SCAN_BLOCKS, 256>>>();

    // after 16 iters (last i=15, odd) the state is in g_S1
    k_final<<<B_, 256>>>(S1, x, Wr, br, lng, lnb, W1, b1, W2, b2, out);
}